// round 4
// baseline (speedup 1.0000x reference)
#include <cuda_runtime.h>
#include <cuda_bf16.h>

#define N_NODES 100000
#define MAX_E   1600000

// ---------------- scratch (static device globals; no allocation) ------------
__device__ __align__(16) float g_deg[N_NODES];        // in-degree (float)
__device__ __align__(16) float g_agg1[N_NODES * 64];  // layer-1 neighbor sum
__device__ __align__(16) float g_h[N_NODES * 64];     // layer-1 output (post-relu)
__device__ __align__(16) float g_p[N_NODES * 32];     // h @ W2l^T (layer-2 messages)
__device__ __align__(16) float g_agg2[N_NODES * 32];  // layer-2 neighbor sum
__device__ __align__(16) int2  g_edges[MAX_E];        // packed (src, dst)

// ---------------- weights in constant memory (uniform-access port) ----------
__constant__ float cW1l[64 * 64];   // [j][k] row-major
__constant__ float cW1r[64 * 64];
__constant__ float cW2l[32 * 64];
__constant__ float cW2r[32 * 64];
__constant__ float cb1[64];
__constant__ float cb2[32];

// ---------------- K0: zero scratch ------------------------------------------
__global__ __launch_bounds__(256) void zero_kernel()
{
    const int n_deg  = N_NODES / 4;            // 25000 float4
    const int n_a1   = N_NODES * 16;           // 1.6M float4
    const int n_a2   = N_NODES * 8;            // 0.8M float4
    const int total  = n_deg + n_a1 + n_a2;
    float4 z = make_float4(0.f, 0.f, 0.f, 0.f);
    for (int t = blockIdx.x * blockDim.x + threadIdx.x; t < total;
         t += gridDim.x * blockDim.x) {
        if (t < n_deg) {
            reinterpret_cast<float4*>(g_deg)[t] = z;
        } else if (t < n_deg + n_a1) {
            reinterpret_cast<float4*>(g_agg1)[t - n_deg] = z;
        } else {
            reinterpret_cast<float4*>(g_agg2)[t - n_deg - n_a1] = z;
        }
    }
}

// ---------------- K1: pack int32 edges -> int2, accumulate degree -----------
__global__ __launch_bounds__(256) void pack_edges_kernel(
    const int* __restrict__ ei1, const int* __restrict__ ei2,
    int E1, int E2)
{
    int t = blockIdx.x * blockDim.x + threadIdx.x;
    int E = E1 + E2;
    if (t >= E) return;
    int s, d;
    if (t < E1) { s = ei1[t];      d = ei1[t + E1]; }
    else        { int u = t - E1;  s = ei2[u];  d = ei2[u + E2]; }
    g_edges[t] = make_int2(s, d);
    atomicAdd(&g_deg[d], 1.0f);
}

// ---------------- K2: scatter layer 1 (64 floats/edge) ----------------------
__global__ __launch_bounds__(256) void scatter64_kernel(
    const float4* __restrict__ x4, int total)   // total = E*16
{
    int t = blockIdx.x * blockDim.x + threadIdx.x;
    if (t >= total) return;
    int e = t >> 4, c = t & 15;
    int2 ed = g_edges[e];
    float4 v = x4[ed.x * 16 + c];
    float* dst = &g_agg1[ed.y * 64 + c * 4];
    atomicAdd(dst + 0, v.x);
    atomicAdd(dst + 1, v.y);
    atomicAdd(dst + 2, v.z);
    atomicAdd(dst + 3, v.w);
}

// ---------------- K3a: layer-1 combine (lane = node, weights in constant) ---
// h[n] = relu( (agg1[n]/deg[n]) @ W1l^T + b1 + x[n] @ W1r^T )
__global__ __launch_bounds__(256) void layer1_kernel(const float* __restrict__ x)
{
    int n = blockIdx.x * blockDim.x + threadIdx.x;
    if (n >= N_NODES) return;

    float dinv = 1.0f / fmaxf(g_deg[n], 1.0f);
    const float4* m4 = reinterpret_cast<const float4*>(g_agg1) + n * 16;
    const float4* v4 = reinterpret_cast<const float4*>(x) + n * 16;

    float acc[64];
    #pragma unroll
    for (int j = 0; j < 64; j++) acc[j] = cb1[j];

    for (int kc = 0; kc < 8; kc++) {      // runtime loop (I$-friendly)
        float4 ma = m4[kc * 2], mb = m4[kc * 2 + 1];
        float4 xa = v4[kc * 2], xb = v4[kc * 2 + 1];
        float m_[8] = {ma.x * dinv, ma.y * dinv, ma.z * dinv, ma.w * dinv,
                       mb.x * dinv, mb.y * dinv, mb.z * dinv, mb.w * dinv};
        float x_[8] = {xa.x, xa.y, xa.z, xa.w, xb.x, xb.y, xb.z, xb.w};
        int kb = kc * 8;
        #pragma unroll
        for (int j = 0; j < 64; j++) {
            float a = acc[j];
            #pragma unroll
            for (int t = 0; t < 8; t++) {
                a = fmaf(m_[t], cW1l[j * 64 + kb + t], a);
                a = fmaf(x_[t], cW1r[j * 64 + kb + t], a);
            }
            acc[j] = a;
        }
    }

    float4* hp = reinterpret_cast<float4*>(g_h) + n * 16;
    #pragma unroll
    for (int j = 0; j < 64; j += 4) {
        hp[j >> 2] = make_float4(fmaxf(acc[j], 0.f), fmaxf(acc[j + 1], 0.f),
                                 fmaxf(acc[j + 2], 0.f), fmaxf(acc[j + 3], 0.f));
    }
}

// ---------------- K3b: layer-2 projections (lane = node) --------------------
// g_p[n] = h[n] @ W2l^T        (message to be scattered)
// out[n] = h[n] @ W2r^T + b2   (self term)
__global__ __launch_bounds__(256) void layer2_kernel(float* __restrict__ out)
{
    int n = blockIdx.x * blockDim.x + threadIdx.x;
    if (n >= N_NODES) return;

    const float4* h4 = reinterpret_cast<const float4*>(g_h) + n * 16;

    float p[32], q[32];
    #pragma unroll
    for (int j = 0; j < 32; j++) { p[j] = 0.f; q[j] = cb2[j]; }

    for (int kc = 0; kc < 8; kc++) {
        float4 ha = h4[kc * 2], hb = h4[kc * 2 + 1];
        float h_[8] = {ha.x, ha.y, ha.z, ha.w, hb.x, hb.y, hb.z, hb.w};
        int kb = kc * 8;
        #pragma unroll
        for (int j = 0; j < 32; j++) {
            float pa = p[j], qa = q[j];
            #pragma unroll
            for (int t = 0; t < 8; t++) {
                pa = fmaf(h_[t], cW2l[j * 64 + kb + t], pa);
                qa = fmaf(h_[t], cW2r[j * 64 + kb + t], qa);
            }
            p[j] = pa; q[j] = qa;
        }
    }

    float4* pp = reinterpret_cast<float4*>(g_p) + n * 8;
    float4* op = reinterpret_cast<float4*>(out) + n * 8;
    #pragma unroll
    for (int j = 0; j < 32; j += 4) {
        pp[j >> 2] = make_float4(p[j], p[j + 1], p[j + 2], p[j + 3]);
        op[j >> 2] = make_float4(q[j], q[j + 1], q[j + 2], q[j + 3]);
    }
}

// ---------------- K4: scatter layer 2 (32 floats/edge) ----------------------
__global__ __launch_bounds__(256) void scatter32_kernel(int total)  // total = E*8
{
    int t = blockIdx.x * blockDim.x + threadIdx.x;
    if (t >= total) return;
    int e = t >> 3, c = t & 7;
    int2 ed = g_edges[e];
    const float4* p4 = reinterpret_cast<const float4*>(g_p);
    float4 v = p4[ed.x * 8 + c];
    float* dst = &g_agg2[ed.y * 32 + c * 4];
    atomicAdd(dst + 0, v.x);
    atomicAdd(dst + 1, v.y);
    atomicAdd(dst + 2, v.z);
    atomicAdd(dst + 3, v.w);
}

// ---------------- K5: finalize: out += agg2 / max(deg,1) --------------------
__global__ __launch_bounds__(256) void finalize_kernel(float* __restrict__ out, int n)
{
    int t = blockIdx.x * blockDim.x + threadIdx.x;
    if (t >= n) return;
    int node = t >> 5;
    out[t] += g_agg2[t] * (1.0f / fmaxf(g_deg[node], 1.0f));
}

// ---------------- launch -----------------------------------------------------
extern "C" void kernel_launch(void* const* d_in, const int* in_sizes, int n_in,
                              void* d_out, int out_size)
{
    const float* x    = (const float*)d_in[0];
    const int*   ei1  = (const int*)d_in[1];     // int32 (JAX x64 disabled)
    const int*   ei2  = (const int*)d_in[3];
    const float* W1l  = (const float*)d_in[5];
    const float* b1   = (const float*)d_in[6];
    const float* W1r  = (const float*)d_in[7];
    const float* W2l  = (const float*)d_in[8];
    const float* b2   = (const float*)d_in[9];
    const float* W2r  = (const float*)d_in[10];
    float*       out  = (float*)d_out;

    int E1 = in_sizes[1] / 2;
    int E2 = in_sizes[3] / 2;
    int E  = E1 + E2;

    // weights -> constant memory (device-to-device async copies; capturable)
    cudaMemcpyToSymbolAsync(cW1l, W1l, 64 * 64 * sizeof(float), 0,
                            cudaMemcpyDeviceToDevice, 0);
    cudaMemcpyToSymbolAsync(cW1r, W1r, 64 * 64 * sizeof(float), 0,
                            cudaMemcpyDeviceToDevice, 0);
    cudaMemcpyToSymbolAsync(cW2l, W2l, 32 * 64 * sizeof(float), 0,
                            cudaMemcpyDeviceToDevice, 0);
    cudaMemcpyToSymbolAsync(cW2r, W2r, 32 * 64 * sizeof(float), 0,
                            cudaMemcpyDeviceToDevice, 0);
    cudaMemcpyToSymbolAsync(cb1, b1, 64 * sizeof(float), 0,
                            cudaMemcpyDeviceToDevice, 0);
    cudaMemcpyToSymbolAsync(cb2, b2, 32 * sizeof(float), 0,
                            cudaMemcpyDeviceToDevice, 0);

    // K0: zero scratch
    zero_kernel<<<2048, 256>>>();

    // K1: pack + degree
    pack_edges_kernel<<<(E + 255) / 256, 256>>>(ei1, ei2, E1, E2);

    // K2: scatter x into agg1
    int total1 = E * 16;
    scatter64_kernel<<<(total1 + 255) / 256, 256>>>(
        reinterpret_cast<const float4*>(x), total1);

    // K3a: layer-1 combine -> g_h
    layer1_kernel<<<(N_NODES + 255) / 256, 256>>>(x);

    // K3b: layer-2 projections -> g_p, out(self term)
    layer2_kernel<<<(N_NODES + 255) / 256, 256>>>(out);

    // K4: scatter p into agg2
    int total2 = E * 8;
    scatter32_kernel<<<(total2 + 255) / 256, 256>>>(total2);

    // K5: finalize
    int n_out = N_NODES * 32;
    finalize_kernel<<<(n_out + 255) / 256, 256>>>(out, n_out);
}

// round 5
// speedup vs baseline: 2.3220x; 2.3220x over previous
#include <cuda_runtime.h>
#include <cuda_bf16.h>

#define N_NODES 100000
#define MAX_E   1600000

// ---------------- scratch (static device globals; no allocation) ------------
__device__ __align__(16) float g_deg[N_NODES];        // in-degree (float)
__device__ __align__(16) float g_agg1[N_NODES * 64];  // layer-1 neighbor sum
__device__ __align__(16) float g_h[N_NODES * 64];     // layer-1 output (post-relu)
__device__ __align__(16) float g_p[N_NODES * 32];     // h @ W2l^T (layer-2 messages)
__device__ __align__(16) float g_agg2[N_NODES * 32];  // layer-2 neighbor sum
__device__ __align__(16) int2  g_edges[MAX_E];        // packed (src, dst)

// ---------------- K0: zero scratch ------------------------------------------
__global__ __launch_bounds__(256) void zero_kernel()
{
    const int n_deg  = N_NODES / 4;            // 25000 float4
    const int n_a1   = N_NODES * 16;           // 1.6M float4
    const int n_a2   = N_NODES * 8;            // 0.8M float4
    const int total  = n_deg + n_a1 + n_a2;
    float4 z = make_float4(0.f, 0.f, 0.f, 0.f);
    for (int t = blockIdx.x * blockDim.x + threadIdx.x; t < total;
         t += gridDim.x * blockDim.x) {
        if (t < n_deg) {
            reinterpret_cast<float4*>(g_deg)[t] = z;
        } else if (t < n_deg + n_a1) {
            reinterpret_cast<float4*>(g_agg1)[t - n_deg] = z;
        } else {
            reinterpret_cast<float4*>(g_agg2)[t - n_deg - n_a1] = z;
        }
    }
}

// ---------------- K1: pack int32 edges -> int2, accumulate degree -----------
__global__ __launch_bounds__(256) void pack_edges_kernel(
    const int* __restrict__ ei1, const int* __restrict__ ei2,
    int E1, int E2)
{
    int t = blockIdx.x * blockDim.x + threadIdx.x;
    int E = E1 + E2;
    if (t >= E) return;
    int s, d;
    if (t < E1) { s = ei1[t];      d = ei1[t + E1]; }
    else        { int u = t - E1;  s = ei2[u];  d = ei2[u + E2]; }
    g_edges[t] = make_int2(s, d);
    atomicAdd(&g_deg[d], 1.0f);
}

// ---------------- K2: scatter layer 1 (64 floats/edge) ----------------------
__global__ __launch_bounds__(256) void scatter64_kernel(
    const float4* __restrict__ x4, int total)   // total = E*16
{
    int t = blockIdx.x * blockDim.x + threadIdx.x;
    if (t >= total) return;
    int e = t >> 4, c = t & 15;
    int2 ed = g_edges[e];
    float4 v = x4[ed.x * 16 + c];
    float* dst = &g_agg1[ed.y * 64 + c * 4];
    atomicAdd(dst + 0, v.x);
    atomicAdd(dst + 1, v.y);
    atomicAdd(dst + 2, v.z);
    atomicAdd(dst + 3, v.w);
}

// ---------------- K3a: layer-1 GEMM -----------------------------------------
// h[n] = relu( (agg1[n]/deg[n]) @ W1l^T + x[n] @ W1r^T + b1 )
// Tiled GEMM: 64 nodes x 64 outs per block, 256 threads, 4x4 register tile.
// K=128 processed as two 64-wide stages (stage0: mean vs W1l, stage1: x vs W1r).
__global__ __launch_bounds__(256) void gemm1_kernel(
    const float* __restrict__ x,
    const float* __restrict__ W1l, const float* __restrict__ W1r,
    const float* __restrict__ b1)
{
    __shared__ float sA[64][64];   // sA[k][node]
    __shared__ float sB[64][64];   // sB[k][out]
    __shared__ float sdinv[64];
    __shared__ float sb[64];

    int tid = threadIdx.x;
    int node0 = blockIdx.x * 64;

    if (tid < 64) {
        int gn = node0 + tid;
        float d = (gn < N_NODES) ? g_deg[gn] : 1.0f;
        sdinv[tid] = 1.0f / fmaxf(d, 1.0f);
        sb[tid] = b1[tid];
    }
    __syncthreads();

    int tx = tid & 15, ty = tid >> 4;     // tx: out-group, ty: node-group
    float acc[4][4] = {};

    #pragma unroll
    for (int stage = 0; stage < 2; stage++) {
        const float* Asrc = stage ? x : g_agg1;
        const float* Bsrc = stage ? W1r : W1l;
        #pragma unroll
        for (int i = 0; i < 4; i++) {
            int idx = tid + i * 256;      // 0..1023
            int n = idx >> 4;             // row 0..63
            int c = idx & 15;             // float4 chunk 0..15
            int gn = node0 + n;
            float4 v = (gn < N_NODES)
                ? reinterpret_cast<const float4*>(Asrc)[gn * 16 + c]
                : make_float4(0.f, 0.f, 0.f, 0.f);
            if (stage == 0) {
                float s = sdinv[n];
                v.x *= s; v.y *= s; v.z *= s; v.w *= s;
            }
            sA[c * 4 + 0][n] = v.x; sA[c * 4 + 1][n] = v.y;
            sA[c * 4 + 2][n] = v.z; sA[c * 4 + 3][n] = v.w;
            float4 w = reinterpret_cast<const float4*>(Bsrc)[n * 16 + c];
            sB[c * 4 + 0][n] = w.x; sB[c * 4 + 1][n] = w.y;
            sB[c * 4 + 2][n] = w.z; sB[c * 4 + 3][n] = w.w;
        }
        __syncthreads();

        #pragma unroll 8
        for (int k = 0; k < 64; k++) {
            float4 a4 = *reinterpret_cast<const float4*>(&sA[k][ty * 4]);
            float4 b4 = *reinterpret_cast<const float4*>(&sB[k][tx * 4]);
            float a_[4] = {a4.x, a4.y, a4.z, a4.w};
            float b_[4] = {b4.x, b4.y, b4.z, b4.w};
            #pragma unroll
            for (int i = 0; i < 4; i++)
                #pragma unroll
                for (int j = 0; j < 4; j++)
                    acc[i][j] = fmaf(a_[i], b_[j], acc[i][j]);
        }
        __syncthreads();
    }

    #pragma unroll
    for (int i = 0; i < 4; i++) {
        int gn = node0 + ty * 4 + i;
        if (gn < N_NODES) {
            float4 o;
            o.x = fmaxf(acc[i][0] + sb[tx * 4 + 0], 0.f);
            o.y = fmaxf(acc[i][1] + sb[tx * 4 + 1], 0.f);
            o.z = fmaxf(acc[i][2] + sb[tx * 4 + 2], 0.f);
            o.w = fmaxf(acc[i][3] + sb[tx * 4 + 3], 0.f);
            reinterpret_cast<float4*>(g_h)[gn * 16 + tx] = o;
        }
    }
}

// ---------------- K3b: layer-2 GEMM -----------------------------------------
// cols 0..31:  p[n] = h[n] @ W2l^T          -> g_p
// cols 32..63: q[n] = h[n] @ W2r^T + b2     -> out (self term)
__global__ __launch_bounds__(256) void gemm2_kernel(
    const float* __restrict__ W2l, const float* __restrict__ W2r,
    const float* __restrict__ b2, float* __restrict__ out)
{
    __shared__ float sA[64][64];   // sA[k][node]
    __shared__ float sB[64][64];   // sB[k][out]  (out<32: W2l, out>=32: W2r)
    __shared__ float sb2[32];

    int tid = threadIdx.x;
    int node0 = blockIdx.x * 64;

    if (tid < 32) sb2[tid] = b2[tid];

    int tx = tid & 15, ty = tid >> 4;
    float acc[4][4] = {};

    #pragma unroll
    for (int i = 0; i < 4; i++) {
        int idx = tid + i * 256;
        int n = idx >> 4;
        int c = idx & 15;
        int gn = node0 + n;
        float4 v = (gn < N_NODES)
            ? reinterpret_cast<const float4*>(g_h)[gn * 16 + c]
            : make_float4(0.f, 0.f, 0.f, 0.f);
        sA[c * 4 + 0][n] = v.x; sA[c * 4 + 1][n] = v.y;
        sA[c * 4 + 2][n] = v.z; sA[c * 4 + 3][n] = v.w;
        const float* Bsrc = (n < 32) ? (W2l + n * 64) : (W2r + (n - 32) * 64);
        float4 w = reinterpret_cast<const float4*>(Bsrc)[c];
        sB[c * 4 + 0][n] = w.x; sB[c * 4 + 1][n] = w.y;
        sB[c * 4 + 2][n] = w.z; sB[c * 4 + 3][n] = w.w;
    }
    __syncthreads();

    #pragma unroll 8
    for (int k = 0; k < 64; k++) {
        float4 a4 = *reinterpret_cast<const float4*>(&sA[k][ty * 4]);
        float4 b4 = *reinterpret_cast<const float4*>(&sB[k][tx * 4]);
        float a_[4] = {a4.x, a4.y, a4.z, a4.w};
        float b_[4] = {b4.x, b4.y, b4.z, b4.w};
        #pragma unroll
        for (int i = 0; i < 4; i++)
            #pragma unroll
            for (int j = 0; j < 4; j++)
                acc[i][j] = fmaf(a_[i], b_[j], acc[i][j]);
    }

    #pragma unroll
    for (int i = 0; i < 4; i++) {
        int gn = node0 + ty * 4 + i;
        if (gn < N_NODES) {
            if (tx < 8) {               // p columns 0..31
                float4 o = make_float4(acc[i][0], acc[i][1], acc[i][2], acc[i][3]);
                reinterpret_cast<float4*>(g_p)[gn * 8 + tx] = o;
            } else {                    // q columns 32..63 -> out cols 0..31
                int jc = (tx - 8) * 4;
                float4 o;
                o.x = acc[i][0] + sb2[jc + 0];
                o.y = acc[i][1] + sb2[jc + 1];
                o.z = acc[i][2] + sb2[jc + 2];
                o.w = acc[i][3] + sb2[jc + 3];
                reinterpret_cast<float4*>(out)[gn * 8 + (tx - 8)] = o;
            }
        }
    }
}

// ---------------- K4: scatter layer 2 (32 floats/edge) ----------------------
__global__ __launch_bounds__(256) void scatter32_kernel(int total)  // total = E*8
{
    int t = blockIdx.x * blockDim.x + threadIdx.x;
    if (t >= total) return;
    int e = t >> 3, c = t & 7;
    int2 ed = g_edges[e];
    const float4* p4 = reinterpret_cast<const float4*>(g_p);
    float4 v = p4[ed.x * 8 + c];
    float* dst = &g_agg2[ed.y * 32 + c * 4];
    atomicAdd(dst + 0, v.x);
    atomicAdd(dst + 1, v.y);
    atomicAdd(dst + 2, v.z);
    atomicAdd(dst + 3, v.w);
}

// ---------------- K5: finalize: out += agg2 / max(deg,1) --------------------
__global__ __launch_bounds__(256) void finalize_kernel(float* __restrict__ out, int n)
{
    int t = blockIdx.x * blockDim.x + threadIdx.x;
    if (t >= n) return;
    int node = t >> 5;
    out[t] += g_agg2[t] * (1.0f / fmaxf(g_deg[node], 1.0f));
}

// ---------------- launch -----------------------------------------------------
extern "C" void kernel_launch(void* const* d_in, const int* in_sizes, int n_in,
                              void* d_out, int out_size)
{
    const float* x    = (const float*)d_in[0];
    const int*   ei1  = (const int*)d_in[1];     // int32 (JAX x64 disabled)
    const int*   ei2  = (const int*)d_in[3];
    const float* W1l  = (const float*)d_in[5];
    const float* b1   = (const float*)d_in[6];
    const float* W1r  = (const float*)d_in[7];
    const float* W2l  = (const float*)d_in[8];
    const float* b2   = (const float*)d_in[9];
    const float* W2r  = (const float*)d_in[10];
    float*       out  = (float*)d_out;

    int E1 = in_sizes[1] / 2;
    int E2 = in_sizes[3] / 2;
    int E  = E1 + E2;
    int nblk = (N_NODES + 63) / 64;   // 1563

    // K0: zero scratch
    zero_kernel<<<2048, 256>>>();

    // K1: pack + degree
    pack_edges_kernel<<<(E + 255) / 256, 256>>>(ei1, ei2, E1, E2);

    // K2: scatter x into agg1
    int total1 = E * 16;
    scatter64_kernel<<<(total1 + 255) / 256, 256>>>(
        reinterpret_cast<const float4*>(x), total1);

    // K3a: layer-1 GEMM -> g_h
    gemm1_kernel<<<nblk, 256>>>(x, W1l, W1r, b1);

    // K3b: layer-2 GEMM -> g_p, out(self term)
    gemm2_kernel<<<nblk, 256>>>(W2l, W2r, b2, out);

    // K4: scatter p into agg2
    int total2 = E * 8;
    scatter32_kernel<<<(total2 + 255) / 256, 256>>>(total2);

    // K5: finalize
    int n_out = N_NODES * 32;
    finalize_kernel<<<(n_out + 255) / 256, 256>>>(out, n_out);
}

// round 6
// speedup vs baseline: 3.7306x; 1.6066x over previous
#include <cuda_runtime.h>
#include <cuda_bf16.h>

#define N_NODES 100000
#define MAX_E   1600000

// ---------------- scratch (static device globals; no allocation) ------------
__device__ __align__(16) float g_deg[N_NODES];        // in-degree (float)
__device__ __align__(16) float g_agg1[N_NODES * 64];  // layer-1 neighbor sum
__device__ __align__(16) float g_h[N_NODES * 64];     // layer-1 output (post-relu)
__device__ __align__(16) float g_p[N_NODES * 32];     // h @ W2l^T (layer-2 messages)
__device__ __align__(16) float g_agg2[N_NODES * 32];  // layer-2 neighbor sum
__device__ __align__(16) int2  g_edges[MAX_E];        // packed (src, dst)

// ---------------- K0: zero scratch ------------------------------------------
__global__ __launch_bounds__(256) void zero_kernel()
{
    const int n_deg  = N_NODES / 4;            // 25000 float4
    const int n_a1   = N_NODES * 16;           // 1.6M float4
    const int n_a2   = N_NODES * 8;            // 0.8M float4
    const int total  = n_deg + n_a1 + n_a2;
    float4 z = make_float4(0.f, 0.f, 0.f, 0.f);
    for (int t = blockIdx.x * blockDim.x + threadIdx.x; t < total;
         t += gridDim.x * blockDim.x) {
        if (t < n_deg) {
            reinterpret_cast<float4*>(g_deg)[t] = z;
        } else if (t < n_deg + n_a1) {
            reinterpret_cast<float4*>(g_agg1)[t - n_deg] = z;
        } else {
            reinterpret_cast<float4*>(g_agg2)[t - n_deg - n_a1] = z;
        }
    }
}

// ---------------- K1: pack int32 edges -> int2, accumulate degree -----------
__global__ __launch_bounds__(256) void pack_edges_kernel(
    const int* __restrict__ ei1, const int* __restrict__ ei2,
    int E1, int E2)
{
    int t = blockIdx.x * blockDim.x + threadIdx.x;
    int E = E1 + E2;
    if (t >= E) return;
    int s, d;
    if (t < E1) { s = ei1[t];      d = ei1[t + E1]; }
    else        { int u = t - E1;  s = ei2[u];  d = ei2[u + E2]; }
    g_edges[t] = make_int2(s, d);
    atomicAdd(&g_deg[d], 1.0f);
}

// ---------------- K2: scatter layer 1 (64 floats/edge, vector REDs) ---------
__global__ __launch_bounds__(256) void scatter64_kernel(
    const float4* __restrict__ x4, int total)   // total = E*16
{
    int t = blockIdx.x * blockDim.x + threadIdx.x;
    if (t >= total) return;
    int e = t >> 4, c = t & 15;
    int2 ed = g_edges[e];
    float4 v = x4[ed.x * 16 + c];
    float4* dst = reinterpret_cast<float4*>(&g_agg1[ed.y * 64 + c * 4]);
    atomicAdd(dst, v);   // RED.E.ADD.F32x4 (sm_90+)
}

// ---------------- K3a: layer-1 GEMM -----------------------------------------
// h[n] = relu( (agg1[n]/deg[n]) @ W1l^T + x[n] @ W1r^T + b1 )
// Tiled GEMM: 64 nodes x 64 outs per block, 256 threads, 4x4 register tile.
__global__ __launch_bounds__(256) void gemm1_kernel(
    const float* __restrict__ x,
    const float* __restrict__ W1l, const float* __restrict__ W1r,
    const float* __restrict__ b1)
{
    __shared__ float sA[64][64];   // sA[k][node]
    __shared__ float sB[64][64];   // sB[k][out]
    __shared__ float sdinv[64];
    __shared__ float sb[64];

    int tid = threadIdx.x;
    int node0 = blockIdx.x * 64;

    if (tid < 64) {
        int gn = node0 + tid;
        float d = (gn < N_NODES) ? g_deg[gn] : 1.0f;
        sdinv[tid] = 1.0f / fmaxf(d, 1.0f);
        sb[tid] = b1[tid];
    }
    __syncthreads();

    int tx = tid & 15, ty = tid >> 4;     // tx: out-group, ty: node-group
    float acc[4][4] = {};

    #pragma unroll
    for (int stage = 0; stage < 2; stage++) {
        const float* Asrc = stage ? x : g_agg1;
        const float* Bsrc = stage ? W1r : W1l;
        #pragma unroll
        for (int i = 0; i < 4; i++) {
            int idx = tid + i * 256;      // 0..1023
            int n = idx >> 4;             // row 0..63
            int c = idx & 15;             // float4 chunk 0..15
            int gn = node0 + n;
            float4 v = (gn < N_NODES)
                ? reinterpret_cast<const float4*>(Asrc)[gn * 16 + c]
                : make_float4(0.f, 0.f, 0.f, 0.f);
            if (stage == 0) {
                float s = sdinv[n];
                v.x *= s; v.y *= s; v.z *= s; v.w *= s;
            }
            sA[c * 4 + 0][n] = v.x; sA[c * 4 + 1][n] = v.y;
            sA[c * 4 + 2][n] = v.z; sA[c * 4 + 3][n] = v.w;
            float4 w = reinterpret_cast<const float4*>(Bsrc)[n * 16 + c];
            sB[c * 4 + 0][n] = w.x; sB[c * 4 + 1][n] = w.y;
            sB[c * 4 + 2][n] = w.z; sB[c * 4 + 3][n] = w.w;
        }
        __syncthreads();

        #pragma unroll 8
        for (int k = 0; k < 64; k++) {
            float4 a4 = *reinterpret_cast<const float4*>(&sA[k][ty * 4]);
            float4 b4 = *reinterpret_cast<const float4*>(&sB[k][tx * 4]);
            float a_[4] = {a4.x, a4.y, a4.z, a4.w};
            float b_[4] = {b4.x, b4.y, b4.z, b4.w};
            #pragma unroll
            for (int i = 0; i < 4; i++)
                #pragma unroll
                for (int j = 0; j < 4; j++)
                    acc[i][j] = fmaf(a_[i], b_[j], acc[i][j]);
        }
        __syncthreads();
    }

    #pragma unroll
    for (int i = 0; i < 4; i++) {
        int gn = node0 + ty * 4 + i;
        if (gn < N_NODES) {
            float4 o;
            o.x = fmaxf(acc[i][0] + sb[tx * 4 + 0], 0.f);
            o.y = fmaxf(acc[i][1] + sb[tx * 4 + 1], 0.f);
            o.z = fmaxf(acc[i][2] + sb[tx * 4 + 2], 0.f);
            o.w = fmaxf(acc[i][3] + sb[tx * 4 + 3], 0.f);
            reinterpret_cast<float4*>(g_h)[gn * 16 + tx] = o;
        }
    }
}

// ---------------- K3b: layer-2 GEMM -----------------------------------------
// cols 0..31:  p[n] = h[n] @ W2l^T          -> g_p
// cols 32..63: q[n] = h[n] @ W2r^T + b2     -> out (self term)
__global__ __launch_bounds__(256) void gemm2_kernel(
    const float* __restrict__ W2l, const float* __restrict__ W2r,
    const float* __restrict__ b2, float* __restrict__ out)
{
    __shared__ float sA[64][64];   // sA[k][node]
    __shared__ float sB[64][64];   // sB[k][out]  (out<32: W2l, out>=32: W2r)
    __shared__ float sb2[32];

    int tid = threadIdx.x;
    int node0 = blockIdx.x * 64;

    if (tid < 32) sb2[tid] = b2[tid];

    int tx = tid & 15, ty = tid >> 4;
    float acc[4][4] = {};

    #pragma unroll
    for (int i = 0; i < 4; i++) {
        int idx = tid + i * 256;
        int n = idx >> 4;
        int c = idx & 15;
        int gn = node0 + n;
        float4 v = (gn < N_NODES)
            ? reinterpret_cast<const float4*>(g_h)[gn * 16 + c]
            : make_float4(0.f, 0.f, 0.f, 0.f);
        sA[c * 4 + 0][n] = v.x; sA[c * 4 + 1][n] = v.y;
        sA[c * 4 + 2][n] = v.z; sA[c * 4 + 3][n] = v.w;
        const float* Bsrc = (n < 32) ? (W2l + n * 64) : (W2r + (n - 32) * 64);
        float4 w = reinterpret_cast<const float4*>(Bsrc)[c];
        sB[c * 4 + 0][n] = w.x; sB[c * 4 + 1][n] = w.y;
        sB[c * 4 + 2][n] = w.z; sB[c * 4 + 3][n] = w.w;
    }
    __syncthreads();

    #pragma unroll 8
    for (int k = 0; k < 64; k++) {
        float4 a4 = *reinterpret_cast<const float4*>(&sA[k][ty * 4]);
        float4 b4 = *reinterpret_cast<const float4*>(&sB[k][tx * 4]);
        float a_[4] = {a4.x, a4.y, a4.z, a4.w};
        float b_[4] = {b4.x, b4.y, b4.z, b4.w};
        #pragma unroll
        for (int i = 0; i < 4; i++)
            #pragma unroll
            for (int j = 0; j < 4; j++)
                acc[i][j] = fmaf(a_[i], b_[j], acc[i][j]);
    }

    #pragma unroll
    for (int i = 0; i < 4; i++) {
        int gn = node0 + ty * 4 + i;
        if (gn < N_NODES) {
            if (tx < 8) {               // p columns 0..31
                float4 o = make_float4(acc[i][0], acc[i][1], acc[i][2], acc[i][3]);
                reinterpret_cast<float4*>(g_p)[gn * 8 + tx] = o;
            } else {                    // q columns 32..63 -> out cols 0..31
                int jc = (tx - 8) * 4;
                float4 o;
                o.x = acc[i][0] + sb2[jc + 0];
                o.y = acc[i][1] + sb2[jc + 1];
                o.z = acc[i][2] + sb2[jc + 2];
                o.w = acc[i][3] + sb2[jc + 3];
                reinterpret_cast<float4*>(out)[gn * 8 + (tx - 8)] = o;
            }
        }
    }
}

// ---------------- K4: scatter layer 2 (32 floats/edge, vector REDs) ---------
__global__ __launch_bounds__(256) void scatter32_kernel(int total)  // total = E*8
{
    int t = blockIdx.x * blockDim.x + threadIdx.x;
    if (t >= total) return;
    int e = t >> 3, c = t & 7;
    int2 ed = g_edges[e];
    const float4* p4 = reinterpret_cast<const float4*>(g_p);
    float4 v = p4[ed.x * 8 + c];
    float4* dst = reinterpret_cast<float4*>(&g_agg2[ed.y * 32 + c * 4]);
    atomicAdd(dst, v);   // RED.E.ADD.F32x4 (sm_90+)
}

// ---------------- K5: finalize: out += agg2 / max(deg,1) --------------------
__global__ __launch_bounds__(256) void finalize_kernel(float* __restrict__ out, int n)
{
    int t = blockIdx.x * blockDim.x + threadIdx.x;
    if (t >= n) return;
    int node = t >> 5;
    out[t] += g_agg2[t] * (1.0f / fmaxf(g_deg[node], 1.0f));
}

// ---------------- launch -----------------------------------------------------
extern "C" void kernel_launch(void* const* d_in, const int* in_sizes, int n_in,
                              void* d_out, int out_size)
{
    const float* x    = (const float*)d_in[0];
    const int*   ei1  = (const int*)d_in[1];     // int32 (JAX x64 disabled)
    const int*   ei2  = (const int*)d_in[3];
    const float* W1l  = (const float*)d_in[5];
    const float* b1   = (const float*)d_in[6];
    const float* W1r  = (const float*)d_in[7];
    const float* W2l  = (const float*)d_in[8];
    const float* b2   = (const float*)d_in[9];
    const float* W2r  = (const float*)d_in[10];
    float*       out  = (float*)d_out;

    int E1 = in_sizes[1] / 2;
    int E2 = in_sizes[3] / 2;
    int E  = E1 + E2;
    int nblk = (N_NODES + 63) / 64;   // 1563

    // K0: zero scratch
    zero_kernel<<<2048, 256>>>();

    // K1: pack + degree
    pack_edges_kernel<<<(E + 255) / 256, 256>>>(ei1, ei2, E1, E2);

    // K2: scatter x into agg1
    int total1 = E * 16;
    scatter64_kernel<<<(total1 + 255) / 256, 256>>>(
        reinterpret_cast<const float4*>(x), total1);

    // K3a: layer-1 GEMM -> g_h
    gemm1_kernel<<<nblk, 256>>>(x, W1l, W1r, b1);

    // K3b: layer-2 GEMM -> g_p, out(self term)
    gemm2_kernel<<<nblk, 256>>>(W2l, W2r, b2, out);

    // K4: scatter p into agg2
    int total2 = E * 8;
    scatter32_kernel<<<(total2 + 255) / 256, 256>>>(total2);

    // K5: finalize
    int n_out = N_NODES * 32;
    finalize_kernel<<<(n_out + 255) / 256, 256>>>(out, n_out);
}

// round 7
// speedup vs baseline: 3.8523x; 1.0326x over previous
#include <cuda_runtime.h>
#include <cuda_bf16.h>

#define N_NODES 100000
#define MAX_E   1600000

// ---------------- scratch (static device globals; no allocation) ------------
__device__ __align__(16) float g_deg[N_NODES];        // in-degree (float)
__device__ __align__(16) float g_agg1[N_NODES * 64];  // layer-1 neighbor sum
__device__ __align__(16) float g_p[N_NODES * 32];     // h @ W2l^T (layer-2 messages)
__device__ __align__(16) float g_agg2[N_NODES * 32];  // layer-2 neighbor sum
__device__ __align__(16) int2  g_edges[MAX_E];        // packed (src, dst)

// ---------------- K0: zero scratch ------------------------------------------
__global__ __launch_bounds__(256) void zero_kernel()
{
    const int n_deg  = N_NODES / 4;            // 25000 float4
    const int n_a1   = N_NODES * 16;           // 1.6M float4
    const int n_a2   = N_NODES * 8;            // 0.8M float4
    const int total  = n_deg + n_a1 + n_a2;
    float4 z = make_float4(0.f, 0.f, 0.f, 0.f);
    for (int t = blockIdx.x * blockDim.x + threadIdx.x; t < total;
         t += gridDim.x * blockDim.x) {
        if (t < n_deg) {
            reinterpret_cast<float4*>(g_deg)[t] = z;
        } else if (t < n_deg + n_a1) {
            reinterpret_cast<float4*>(g_agg1)[t - n_deg] = z;
        } else {
            reinterpret_cast<float4*>(g_agg2)[t - n_deg - n_a1] = z;
        }
    }
}

// ---------------- K1: pack int32 edges -> int2, accumulate degree -----------
__global__ __launch_bounds__(256) void pack_edges_kernel(
    const int* __restrict__ ei1, const int* __restrict__ ei2,
    int E1, int E2)
{
    int t = blockIdx.x * blockDim.x + threadIdx.x;
    int E = E1 + E2;
    if (t >= E) return;
    int s, d;
    if (t < E1) { s = ei1[t];      d = ei1[t + E1]; }
    else        { int u = t - E1;  s = ei2[u];  d = ei2[u + E2]; }
    g_edges[t] = make_int2(s, d);
    atomicAdd(&g_deg[d], 1.0f);
}

// ---------------- K2: scatter layer 1 (64 floats/edge, vector REDs) ---------
__global__ __launch_bounds__(256) void scatter64_kernel(
    const float4* __restrict__ x4, int total)   // total = E*16
{
    int t = blockIdx.x * blockDim.x + threadIdx.x;
    if (t >= total) return;
    int e = t >> 4, c = t & 15;
    int2 ed = g_edges[e];
    float4 v = x4[ed.x * 16 + c];
    float4* dst = reinterpret_cast<float4*>(&g_agg1[ed.y * 64 + c * 4]);
    atomicAdd(dst, v);   // RED.E.ADD.F32x4
}

// ---------------- K3: fused two-layer GEMM -----------------------------------
// Per block: 128 nodes.
//   Stage A: h = relu( (agg1/deg) @ W1l^T + x @ W1r^T + b1 )   -> smem (reuse sA)
//   Stage B: p = h @ W2l^T -> g_p ;  q = h @ W2r^T + b2 -> out
// 256 threads, 8x4 register tile (128 nodes x 64 outs).
__global__ __launch_bounds__(256) void fused_gemm_kernel(
    const float* __restrict__ x,
    const float* __restrict__ W1l, const float* __restrict__ W1r,
    const float* __restrict__ b1,
    const float* __restrict__ W2l, const float* __restrict__ W2r,
    const float* __restrict__ b2,
    float* __restrict__ out)
{
    __shared__ float sA[64][128];   // stage A: operand tile; stage B: h tile
    __shared__ float sB[64][64];    // weight tile (transposed: [k][out])
    __shared__ float sdinv[128];
    __shared__ float sb1[64];
    __shared__ float sb2[32];

    int tid = threadIdx.x;
    int node0 = blockIdx.x * 128;

    if (tid < 128) {
        int gn = node0 + tid;
        float d = (gn < N_NODES) ? g_deg[gn] : 1.0f;
        sdinv[tid] = 1.0f / fmaxf(d, 1.0f);
    }
    if (tid < 64) sb1[tid] = b1[tid];
    if (tid >= 64 && tid < 96) sb2[tid - 64] = b2[tid - 64];
    __syncthreads();

    int tx = tid & 15, ty = tid >> 4;   // tx: out-group (16x4), ty: node-group (16x8)
    float acc[8][4] = {};

    // ---------------- Stage A: layer-1 GEMM ---------------------------------
    #pragma unroll
    for (int stage = 0; stage < 2; stage++) {
        const float* Asrc = stage ? x : g_agg1;
        const float* Bsrc = stage ? W1r : W1l;
        // load A: 128 nodes x 64 k = 2048 float4, 8 per thread
        #pragma unroll
        for (int i = 0; i < 8; i++) {
            int idx = tid + i * 256;        // 0..2047
            int n = idx >> 4;               // node row 0..127
            int c = idx & 15;               // float4 chunk
            int gn = node0 + n;
            float4 v = (gn < N_NODES)
                ? reinterpret_cast<const float4*>(Asrc)[gn * 16 + c]
                : make_float4(0.f, 0.f, 0.f, 0.f);
            if (stage == 0) {
                float s = sdinv[n];
                v.x *= s; v.y *= s; v.z *= s; v.w *= s;
            }
            sA[c * 4 + 0][n] = v.x; sA[c * 4 + 1][n] = v.y;
            sA[c * 4 + 2][n] = v.z; sA[c * 4 + 3][n] = v.w;
        }
        // load B: 64x64 = 1024 float4, 4 per thread
        #pragma unroll
        for (int i = 0; i < 4; i++) {
            int idx = tid + i * 256;
            int j = idx >> 4;
            int c = idx & 15;
            float4 w = reinterpret_cast<const float4*>(Bsrc)[j * 16 + c];
            sB[c * 4 + 0][j] = w.x; sB[c * 4 + 1][j] = w.y;
            sB[c * 4 + 2][j] = w.z; sB[c * 4 + 3][j] = w.w;
        }
        __syncthreads();

        #pragma unroll 8
        for (int k = 0; k < 64; k++) {
            float4 a4a = *reinterpret_cast<const float4*>(&sA[k][ty * 8]);
            float4 a4b = *reinterpret_cast<const float4*>(&sA[k][ty * 8 + 4]);
            float4 b4  = *reinterpret_cast<const float4*>(&sB[k][tx * 4]);
            float a_[8] = {a4a.x, a4a.y, a4a.z, a4a.w, a4b.x, a4b.y, a4b.z, a4b.w};
            float b_[4] = {b4.x, b4.y, b4.z, b4.w};
            #pragma unroll
            for (int i = 0; i < 8; i++)
                #pragma unroll
                for (int j = 0; j < 4; j++)
                    acc[i][j] = fmaf(a_[i], b_[j], acc[i][j]);
        }
        __syncthreads();
    }

    // relu + bias, write h into sA as [out_k][node]
    #pragma unroll
    for (int i = 0; i < 8; i++) {
        int n = ty * 8 + i;
        #pragma unroll
        for (int j = 0; j < 4; j++)
            sA[tx * 4 + j][n] = fmaxf(acc[i][j] + sb1[tx * 4 + j], 0.f);
    }

    // load stacked W2 (rows 0..31: W2l, 32..63: W2r)
    #pragma unroll
    for (int i = 0; i < 4; i++) {
        int idx = tid + i * 256;
        int j = idx >> 4;
        int c = idx & 15;
        const float* Bsrc = (j < 32) ? (W2l + j * 64) : (W2r + (j - 32) * 64);
        float4 w = reinterpret_cast<const float4*>(Bsrc)[c];
        sB[c * 4 + 0][j] = w.x; sB[c * 4 + 1][j] = w.y;
        sB[c * 4 + 2][j] = w.z; sB[c * 4 + 3][j] = w.w;
    }
    __syncthreads();

    // ---------------- Stage B: layer-2 GEMM ---------------------------------
    float acc2[8][4] = {};
    #pragma unroll 8
    for (int k = 0; k < 64; k++) {
        float4 a4a = *reinterpret_cast<const float4*>(&sA[k][ty * 8]);
        float4 a4b = *reinterpret_cast<const float4*>(&sA[k][ty * 8 + 4]);
        float4 b4  = *reinterpret_cast<const float4*>(&sB[k][tx * 4]);
        float a_[8] = {a4a.x, a4a.y, a4a.z, a4a.w, a4b.x, a4b.y, a4b.z, a4b.w};
        float b_[4] = {b4.x, b4.y, b4.z, b4.w};
        #pragma unroll
        for (int i = 0; i < 8; i++)
            #pragma unroll
            for (int j = 0; j < 4; j++)
                acc2[i][j] = fmaf(a_[i], b_[j], acc2[i][j]);
    }

    #pragma unroll
    for (int i = 0; i < 8; i++) {
        int gn = node0 + ty * 8 + i;
        if (gn < N_NODES) {
            if (tx < 8) {               // p columns 0..31 -> g_p
                float4 o = make_float4(acc2[i][0], acc2[i][1], acc2[i][2], acc2[i][3]);
                reinterpret_cast<float4*>(g_p)[gn * 8 + tx] = o;
            } else {                    // q columns -> out (self term + b2)
                int jc = (tx - 8) * 4;
                float4 o;
                o.x = acc2[i][0] + sb2[jc + 0];
                o.y = acc2[i][1] + sb2[jc + 1];
                o.z = acc2[i][2] + sb2[jc + 2];
                o.w = acc2[i][3] + sb2[jc + 3];
                reinterpret_cast<float4*>(out)[gn * 8 + (tx - 8)] = o;
            }
        }
    }
}

// ---------------- K4: scatter layer 2 (32 floats/edge, vector REDs) ---------
__global__ __launch_bounds__(256) void scatter32_kernel(int total)  // total = E*8
{
    int t = blockIdx.x * blockDim.x + threadIdx.x;
    if (t >= total) return;
    int e = t >> 3, c = t & 7;
    int2 ed = g_edges[e];
    const float4* p4 = reinterpret_cast<const float4*>(g_p);
    float4 v = p4[ed.x * 8 + c];
    float4* dst = reinterpret_cast<float4*>(&g_agg2[ed.y * 32 + c * 4]);
    atomicAdd(dst, v);   // RED.E.ADD.F32x4
}

// ---------------- K5: finalize: out += agg2 / max(deg,1) --------------------
__global__ __launch_bounds__(256) void finalize_kernel(float* __restrict__ out, int n)
{
    int t = blockIdx.x * blockDim.x + threadIdx.x;
    if (t >= n) return;
    int node = t >> 5;
    out[t] += g_agg2[t] * (1.0f / fmaxf(g_deg[node], 1.0f));
}

// ---------------- launch -----------------------------------------------------
extern "C" void kernel_launch(void* const* d_in, const int* in_sizes, int n_in,
                              void* d_out, int out_size)
{
    const float* x    = (const float*)d_in[0];
    const int*   ei1  = (const int*)d_in[1];     // int32 (JAX x64 disabled)
    const int*   ei2  = (const int*)d_in[3];
    const float* W1l  = (const float*)d_in[5];
    const float* b1   = (const float*)d_in[6];
    const float* W1r  = (const float*)d_in[7];
    const float* W2l  = (const float*)d_in[8];
    const float* b2   = (const float*)d_in[9];
    const float* W2r  = (const float*)d_in[10];
    float*       out  = (float*)d_out;

    int E1 = in_sizes[1] / 2;
    int E2 = in_sizes[3] / 2;
    int E  = E1 + E2;

    // K0: zero scratch
    zero_kernel<<<2048, 256>>>();

    // K1: pack + degree
    pack_edges_kernel<<<(E + 255) / 256, 256>>>(ei1, ei2, E1, E2);

    // K2: scatter x into agg1
    int total1 = E * 16;
    scatter64_kernel<<<(total1 + 255) / 256, 256>>>(
        reinterpret_cast<const float4*>(x), total1);

    // K3: fused two-layer GEMM -> g_p, out(self term)
    int nblk = (N_NODES + 127) / 128;   // 782
    fused_gemm_kernel<<<nblk, 256>>>(x, W1l, W1r, b1, W2l, W2r, b2, out);

    // K4: scatter p into agg2
    int total2 = E * 8;
    scatter32_kernel<<<(total2 + 255) / 256, 256>>>(total2);

    // K5: finalize
    int n_out = N_NODES * 32;
    finalize_kernel<<<(n_out + 255) / 256, 256>>>(out, n_out);
}

// round 8
// speedup vs baseline: 4.8741x; 1.2653x over previous
#include <cuda_runtime.h>
#include <cuda_bf16.h>

#define N_NODES 100000
#define MAX_E   1600000
#define NB_SCAN 98            // ceil(100000/1024)

// ---------------- scratch (static device globals; no allocation) ------------
__device__ __align__(16) int   g_degi[N_NODES];        // in-degree (int)
__device__ __align__(16) int   g_rowptr[N_NODES + 1];  // CSR row offsets
__device__ __align__(16) int   g_fill[N_NODES];        // fill cursor
__device__ __align__(16) int   g_blocksum[NB_SCAN + 1];
__device__ __align__(16) int   g_blockoff[NB_SCAN + 1];
__device__ __align__(16) int   g_csr_src[MAX_E];       // src per CSR slot
__device__ __align__(16) float g_mean[N_NODES * 64];   // layer-1 neighbor mean
__device__ __align__(16) float g_p[N_NODES * 32];      // h @ W2l^T (l2 messages)

// ---------------- K0: zero degree counters ----------------------------------
__global__ __launch_bounds__(256) void zero_deg_kernel()
{
    int t = blockIdx.x * blockDim.x + threadIdx.x;
    if (t < N_NODES) g_degi[t] = 0;
}

// ---------------- K1: count in-degrees ---------------------------------------
__global__ __launch_bounds__(256) void count_deg_kernel(
    const int* __restrict__ ei1, const int* __restrict__ ei2, int E1, int E2)
{
    int t = blockIdx.x * blockDim.x + threadIdx.x;
    int E = E1 + E2;
    if (t >= E) return;
    int d = (t < E1) ? ei1[t + E1] : ei2[(t - E1) + E2];
    atomicAdd(&g_degi[d], 1);
}

// ---------------- K2a: per-block exclusive scan (1024 items/block) ----------
__global__ __launch_bounds__(256) void scan_block_kernel()
{
    __shared__ int swarp[8];
    int tid = threadIdx.x, lane = tid & 31, wid = tid >> 5;
    int base = blockIdx.x * 1024 + tid * 4;

    int v0 = (base + 0 < N_NODES) ? g_degi[base + 0] : 0;
    int v1 = (base + 1 < N_NODES) ? g_degi[base + 1] : 0;
    int v2 = (base + 2 < N_NODES) ? g_degi[base + 2] : 0;
    int v3 = (base + 3 < N_NODES) ? g_degi[base + 3] : 0;
    int tsum = v0 + v1 + v2 + v3;

    int s = tsum;
    #pragma unroll
    for (int off = 1; off < 32; off <<= 1) {
        int t = __shfl_up_sync(0xffffffffu, s, off);
        if (lane >= off) s += t;
    }
    if (lane == 31) swarp[wid] = s;
    __syncthreads();
    if (tid == 0) {
        int r = 0;
        #pragma unroll
        for (int i = 0; i < 8; i++) { int t = swarp[i]; swarp[i] = r; r += t; }
        g_blocksum[blockIdx.x] = r;                 // block total
    }
    __syncthreads();
    int excl = s - tsum + swarp[wid];               // exclusive within block
    if (base + 0 < N_NODES) g_rowptr[base + 0] = excl;
    if (base + 1 < N_NODES) g_rowptr[base + 1] = excl + v0;
    if (base + 2 < N_NODES) g_rowptr[base + 2] = excl + v0 + v1;
    if (base + 3 < N_NODES) g_rowptr[base + 3] = excl + v0 + v1 + v2;
}

// ---------------- K2b: scan block sums (single block) ------------------------
__global__ __launch_bounds__(128) void scan_sums_kernel()
{
    __shared__ int sw[4];
    int tid = threadIdx.x, lane = tid & 31, wid = tid >> 5;
    int v = (tid < NB_SCAN) ? g_blocksum[tid] : 0;
    int s = v;
    #pragma unroll
    for (int off = 1; off < 32; off <<= 1) {
        int t = __shfl_up_sync(0xffffffffu, s, off);
        if (lane >= off) s += t;
    }
    if (lane == 31) sw[wid] = s;
    __syncthreads();
    if (tid == 0) {
        int r = 0;
        #pragma unroll
        for (int i = 0; i < 4; i++) { int t = sw[i]; sw[i] = r; r += t; }
    }
    __syncthreads();
    if (tid < NB_SCAN) g_blockoff[tid] = s - v + sw[wid];
}

// ---------------- K2c: add block offsets, init fill cursors ------------------
__global__ __launch_bounds__(256) void scan_add_kernel(int E)
{
    int t = blockIdx.x * blockDim.x + threadIdx.x;
    if (t < N_NODES) {
        int val = g_rowptr[t] + g_blockoff[t >> 10];
        g_rowptr[t] = val;
        g_fill[t] = val;
    }
    if (t == N_NODES) g_rowptr[N_NODES] = E;
}

// ---------------- K3: fill CSR slots -----------------------------------------
__global__ __launch_bounds__(256) void fill_csr_kernel(
    const int* __restrict__ ei1, const int* __restrict__ ei2, int E1, int E2)
{
    int t = blockIdx.x * blockDim.x + threadIdx.x;
    int E = E1 + E2;
    if (t >= E) return;
    int s, d;
    if (t < E1) { s = ei1[t];      d = ei1[t + E1]; }
    else        { int u = t - E1;  s = ei2[u];  d = ei2[u + E2]; }
    int pos = atomicAdd(&g_fill[d], 1);
    g_csr_src[pos] = s;
}

// ---------------- K4: gather layer 1 (warp per node) -------------------------
// g_mean[n] = mean over in-edges of x[src]   (64 floats, float2 per lane)
__global__ __launch_bounds__(256) void gather64_kernel(const float* __restrict__ x)
{
    int wid = threadIdx.x >> 5, lane = threadIdx.x & 31;
    int n = blockIdx.x * 8 + wid;
    if (n >= N_NODES) return;

    int start = g_rowptr[n], end = g_rowptr[n + 1];
    const float2* x2 = reinterpret_cast<const float2*>(x);

    float ax = 0.f, ay = 0.f;
    int e = start;
    for (; e + 4 <= end; e += 4) {
        int s0 = g_csr_src[e + 0];
        int s1 = g_csr_src[e + 1];
        int s2 = g_csr_src[e + 2];
        int s3 = g_csr_src[e + 3];
        float2 v0 = __ldg(&x2[s0 * 32 + lane]);
        float2 v1 = __ldg(&x2[s1 * 32 + lane]);
        float2 v2 = __ldg(&x2[s2 * 32 + lane]);
        float2 v3 = __ldg(&x2[s3 * 32 + lane]);
        ax += (v0.x + v1.x) + (v2.x + v3.x);
        ay += (v0.y + v1.y) + (v2.y + v3.y);
    }
    for (; e < end; e++) {
        int s = g_csr_src[e];
        float2 v = __ldg(&x2[s * 32 + lane]);
        ax += v.x; ay += v.y;
    }
    float dinv = (end > start) ? 1.0f / (float)(end - start) : 0.0f;
    reinterpret_cast<float2*>(g_mean)[n * 32 + lane] =
        make_float2(ax * dinv, ay * dinv);
}

// ---------------- K5: fused two-layer GEMM -----------------------------------
// Per block: 128 nodes.
//   Stage A: h = relu( mean @ W1l^T + x @ W1r^T + b1 )  -> smem (reuse sA)
//   Stage B: p = h @ W2l^T -> g_p ;  q = h @ W2r^T + b2 -> out
__global__ __launch_bounds__(256) void fused_gemm_kernel(
    const float* __restrict__ x,
    const float* __restrict__ W1l, const float* __restrict__ W1r,
    const float* __restrict__ b1,
    const float* __restrict__ W2l, const float* __restrict__ W2r,
    const float* __restrict__ b2,
    float* __restrict__ out)
{
    __shared__ float sA[64][128];   // stage A: operand tile; stage B: h tile
    __shared__ float sB[64][64];    // weight tile (transposed: [k][out])
    __shared__ float sb1[64];
    __shared__ float sb2[32];

    int tid = threadIdx.x;
    int node0 = blockIdx.x * 128;

    if (tid < 64) sb1[tid] = b1[tid];
    if (tid >= 64 && tid < 96) sb2[tid - 64] = b2[tid - 64];
    __syncthreads();

    int tx = tid & 15, ty = tid >> 4;
    float acc[8][4] = {};

    #pragma unroll
    for (int stage = 0; stage < 2; stage++) {
        const float* Asrc = stage ? x : g_mean;
        const float* Bsrc = stage ? W1r : W1l;
        #pragma unroll
        for (int i = 0; i < 8; i++) {
            int idx = tid + i * 256;
            int n = idx >> 4;
            int c = idx & 15;
            int gn = node0 + n;
            float4 v = (gn < N_NODES)
                ? reinterpret_cast<const float4*>(Asrc)[gn * 16 + c]
                : make_float4(0.f, 0.f, 0.f, 0.f);
            sA[c * 4 + 0][n] = v.x; sA[c * 4 + 1][n] = v.y;
            sA[c * 4 + 2][n] = v.z; sA[c * 4 + 3][n] = v.w;
        }
        #pragma unroll
        for (int i = 0; i < 4; i++) {
            int idx = tid + i * 256;
            int j = idx >> 4;
            int c = idx & 15;
            float4 w = reinterpret_cast<const float4*>(Bsrc)[j * 16 + c];
            sB[c * 4 + 0][j] = w.x; sB[c * 4 + 1][j] = w.y;
            sB[c * 4 + 2][j] = w.z; sB[c * 4 + 3][j] = w.w;
        }
        __syncthreads();

        #pragma unroll 8
        for (int k = 0; k < 64; k++) {
            float4 a4a = *reinterpret_cast<const float4*>(&sA[k][ty * 8]);
            float4 a4b = *reinterpret_cast<const float4*>(&sA[k][ty * 8 + 4]);
            float4 b4  = *reinterpret_cast<const float4*>(&sB[k][tx * 4]);
            float a_[8] = {a4a.x, a4a.y, a4a.z, a4a.w, a4b.x, a4b.y, a4b.z, a4b.w};
            float b_[4] = {b4.x, b4.y, b4.z, b4.w};
            #pragma unroll
            for (int i = 0; i < 8; i++)
                #pragma unroll
                for (int j = 0; j < 4; j++)
                    acc[i][j] = fmaf(a_[i], b_[j], acc[i][j]);
        }
        __syncthreads();
    }

    // relu + bias, write h into sA as [out_k][node]
    #pragma unroll
    for (int i = 0; i < 8; i++) {
        int n = ty * 8 + i;
        #pragma unroll
        for (int j = 0; j < 4; j++)
            sA[tx * 4 + j][n] = fmaxf(acc[i][j] + sb1[tx * 4 + j], 0.f);
    }

    // load stacked W2 (rows 0..31: W2l, 32..63: W2r)
    #pragma unroll
    for (int i = 0; i < 4; i++) {
        int idx = tid + i * 256;
        int j = idx >> 4;
        int c = idx & 15;
        const float* Bsrc = (j < 32) ? (W2l + j * 64) : (W2r + (j - 32) * 64);
        float4 w = reinterpret_cast<const float4*>(Bsrc)[c];
        sB[c * 4 + 0][j] = w.x; sB[c * 4 + 1][j] = w.y;
        sB[c * 4 + 2][j] = w.z; sB[c * 4 + 3][j] = w.w;
    }
    __syncthreads();

    float acc2[8][4] = {};
    #pragma unroll 8
    for (int k = 0; k < 64; k++) {
        float4 a4a = *reinterpret_cast<const float4*>(&sA[k][ty * 8]);
        float4 a4b = *reinterpret_cast<const float4*>(&sA[k][ty * 8 + 4]);
        float4 b4  = *reinterpret_cast<const float4*>(&sB[k][tx * 4]);
        float a_[8] = {a4a.x, a4a.y, a4a.z, a4a.w, a4b.x, a4b.y, a4b.z, a4b.w};
        float b_[4] = {b4.x, b4.y, b4.z, b4.w};
        #pragma unroll
        for (int i = 0; i < 8; i++)
            #pragma unroll
            for (int j = 0; j < 4; j++)
                acc2[i][j] = fmaf(a_[i], b_[j], acc2[i][j]);
    }

    #pragma unroll
    for (int i = 0; i < 8; i++) {
        int gn = node0 + ty * 8 + i;
        if (gn < N_NODES) {
            if (tx < 8) {               // p columns -> g_p
                float4 o = make_float4(acc2[i][0], acc2[i][1], acc2[i][2], acc2[i][3]);
                reinterpret_cast<float4*>(g_p)[gn * 8 + tx] = o;
            } else {                    // q columns -> out (self term + b2)
                int jc = (tx - 8) * 4;
                float4 o;
                o.x = acc2[i][0] + sb2[jc + 0];
                o.y = acc2[i][1] + sb2[jc + 1];
                o.z = acc2[i][2] + sb2[jc + 2];
                o.w = acc2[i][3] + sb2[jc + 3];
                reinterpret_cast<float4*>(out)[gn * 8 + (tx - 8)] = o;
            }
        }
    }
}

// ---------------- K6: gather layer 2 (warp per node) -------------------------
// out[n] += mean over in-edges of g_p[src]   (32 floats, 1 per lane; exclusive)
__global__ __launch_bounds__(256) void gather32_kernel(float* __restrict__ out)
{
    int wid = threadIdx.x >> 5, lane = threadIdx.x & 31;
    int n = blockIdx.x * 8 + wid;
    if (n >= N_NODES) return;

    int start = g_rowptr[n], end = g_rowptr[n + 1];

    float a = 0.f;
    int e = start;
    for (; e + 4 <= end; e += 4) {
        int s0 = g_csr_src[e + 0];
        int s1 = g_csr_src[e + 1];
        int s2 = g_csr_src[e + 2];
        int s3 = g_csr_src[e + 3];
        float v0 = __ldg(&g_p[s0 * 32 + lane]);
        float v1 = __ldg(&g_p[s1 * 32 + lane]);
        float v2 = __ldg(&g_p[s2 * 32 + lane]);
        float v3 = __ldg(&g_p[s3 * 32 + lane]);
        a += (v0 + v1) + (v2 + v3);
    }
    for (; e < end; e++) {
        int s = g_csr_src[e];
        a += __ldg(&g_p[s * 32 + lane]);
    }
    float dinv = (end > start) ? 1.0f / (float)(end - start) : 0.0f;
    out[n * 32 + lane] += a * dinv;
}

// ---------------- launch ------------------------------------------------------
extern "C" void kernel_launch(void* const* d_in, const int* in_sizes, int n_in,
                              void* d_out, int out_size)
{
    const float* x    = (const float*)d_in[0];
    const int*   ei1  = (const int*)d_in[1];     // int32 (JAX x64 disabled)
    const int*   ei2  = (const int*)d_in[3];
    const float* W1l  = (const float*)d_in[5];
    const float* b1   = (const float*)d_in[6];
    const float* W1r  = (const float*)d_in[7];
    const float* W2l  = (const float*)d_in[8];
    const float* b2   = (const float*)d_in[9];
    const float* W2r  = (const float*)d_in[10];
    float*       out  = (float*)d_out;

    int E1 = in_sizes[1] / 2;
    int E2 = in_sizes[3] / 2;
    int E  = E1 + E2;

    // CSR build
    zero_deg_kernel<<<(N_NODES + 255) / 256, 256>>>();
    count_deg_kernel<<<(E + 255) / 256, 256>>>(ei1, ei2, E1, E2);
    scan_block_kernel<<<NB_SCAN, 256>>>();
    scan_sums_kernel<<<1, 128>>>();
    scan_add_kernel<<<(N_NODES + 256) / 256, 256>>>(E);
    fill_csr_kernel<<<(E + 255) / 256, 256>>>(ei1, ei2, E1, E2);

    // layer-1 aggregation (gather, no atomics)
    gather64_kernel<<<(N_NODES + 7) / 8, 256>>>(x);

    // fused two-layer GEMM -> g_p, out(self term)
    int nblk = (N_NODES + 127) / 128;
    fused_gemm_kernel<<<nblk, 256>>>(x, W1l, W1r, b1, W2l, W2r, b2, out);

    // layer-2 aggregation (gather, exclusive out += mean)
    gather32_kernel<<<(N_NODES + 7) / 8, 256>>>(out);
}

// round 9
// speedup vs baseline: 4.9245x; 1.0103x over previous
#include <cuda_runtime.h>
#include <cuda_bf16.h>

#define N_NODES 100000
#define MAX_E   1600000
#define NB_SCAN 98            // ceil(100000/1024)

// ---------------- scratch (static device globals; no allocation) ------------
__device__ __align__(16) int   g_degi[N_NODES];        // in-degree (int)
__device__ __align__(16) int   g_rowptr[N_NODES + 1];  // CSR row offsets
__device__ __align__(16) int   g_fill[N_NODES];        // fill cursor
__device__ __align__(16) int   g_blocksum[NB_SCAN + 1];
__device__ __align__(16) int   g_blockoff[NB_SCAN + 1];
__device__ __align__(16) int   g_csr_src[MAX_E];       // src per CSR slot
__device__ __align__(16) float g_mean[N_NODES * 64];   // layer-1 neighbor mean
__device__ __align__(16) float g_p[N_NODES * 32];      // h @ W2l^T (l2 messages)

// ---------------- K0: zero degree counters ----------------------------------
__global__ __launch_bounds__(256) void zero_deg_kernel()
{
    int t = blockIdx.x * blockDim.x + threadIdx.x;
    if (t < N_NODES) g_degi[t] = 0;
}

// ---------------- K1: count in-degrees ---------------------------------------
__global__ __launch_bounds__(256) void count_deg_kernel(
    const int* __restrict__ ei1, const int* __restrict__ ei2, int E1, int E2)
{
    int t = blockIdx.x * blockDim.x + threadIdx.x;
    int E = E1 + E2;
    if (t >= E) return;
    int d = (t < E1) ? ei1[t + E1] : ei2[(t - E1) + E2];
    atomicAdd(&g_degi[d], 1);
}

// ---------------- K2a: per-block exclusive scan (1024 items/block) ----------
__global__ __launch_bounds__(256) void scan_block_kernel()
{
    __shared__ int swarp[8];
    int tid = threadIdx.x, lane = tid & 31, wid = tid >> 5;
    int base = blockIdx.x * 1024 + tid * 4;

    int v0 = (base + 0 < N_NODES) ? g_degi[base + 0] : 0;
    int v1 = (base + 1 < N_NODES) ? g_degi[base + 1] : 0;
    int v2 = (base + 2 < N_NODES) ? g_degi[base + 2] : 0;
    int v3 = (base + 3 < N_NODES) ? g_degi[base + 3] : 0;
    int tsum = v0 + v1 + v2 + v3;

    int s = tsum;
    #pragma unroll
    for (int off = 1; off < 32; off <<= 1) {
        int t = __shfl_up_sync(0xffffffffu, s, off);
        if (lane >= off) s += t;
    }
    if (lane == 31) swarp[wid] = s;
    __syncthreads();
    if (tid == 0) {
        int r = 0;
        #pragma unroll
        for (int i = 0; i < 8; i++) { int t = swarp[i]; swarp[i] = r; r += t; }
        g_blocksum[blockIdx.x] = r;                 // block total
    }
    __syncthreads();
    int excl = s - tsum + swarp[wid];               // exclusive within block
    if (base + 0 < N_NODES) g_rowptr[base + 0] = excl;
    if (base + 1 < N_NODES) g_rowptr[base + 1] = excl + v0;
    if (base + 2 < N_NODES) g_rowptr[base + 2] = excl + v0 + v1;
    if (base + 3 < N_NODES) g_rowptr[base + 3] = excl + v0 + v1 + v2;
}

// ---------------- K2b: scan block sums (single block) ------------------------
__global__ __launch_bounds__(128) void scan_sums_kernel()
{
    __shared__ int sw[4];
    int tid = threadIdx.x, lane = tid & 31, wid = tid >> 5;
    int v = (tid < NB_SCAN) ? g_blocksum[tid] : 0;
    int s = v;
    #pragma unroll
    for (int off = 1; off < 32; off <<= 1) {
        int t = __shfl_up_sync(0xffffffffu, s, off);
        if (lane >= off) s += t;
    }
    if (lane == 31) sw[wid] = s;
    __syncthreads();
    if (tid == 0) {
        int r = 0;
        #pragma unroll
        for (int i = 0; i < 4; i++) { int t = sw[i]; sw[i] = r; r += t; }
    }
    __syncthreads();
    if (tid < NB_SCAN) g_blockoff[tid] = s - v + sw[wid];
}

// ---------------- K2c: add block offsets, init fill cursors ------------------
__global__ __launch_bounds__(256) void scan_add_kernel(int E)
{
    int t = blockIdx.x * blockDim.x + threadIdx.x;
    if (t < N_NODES) {
        int val = g_rowptr[t] + g_blockoff[t >> 10];
        g_rowptr[t] = val;
        g_fill[t] = val;
    }
    if (t == N_NODES) g_rowptr[N_NODES] = E;
}

// ---------------- K3: fill CSR slots -----------------------------------------
__global__ __launch_bounds__(256) void fill_csr_kernel(
    const int* __restrict__ ei1, const int* __restrict__ ei2, int E1, int E2)
{
    int t = blockIdx.x * blockDim.x + threadIdx.x;
    int E = E1 + E2;
    if (t >= E) return;
    int s, d;
    if (t < E1) { s = ei1[t];      d = ei1[t + E1]; }
    else        { int u = t - E1;  s = ei2[u];  d = ei2[u + E2]; }
    int pos = atomicAdd(&g_fill[d], 1);
    g_csr_src[pos] = s;
}

// ---------------- K4: gather layer 1 (warp per node) -------------------------
__global__ __launch_bounds__(256) void gather64_kernel(const float* __restrict__ x)
{
    int wid = threadIdx.x >> 5, lane = threadIdx.x & 31;
    int n = blockIdx.x * 8 + wid;
    if (n >= N_NODES) return;

    int start = g_rowptr[n], end = g_rowptr[n + 1];
    const float2* x2 = reinterpret_cast<const float2*>(x);

    float ax = 0.f, ay = 0.f;
    int e = start;
    for (; e + 4 <= end; e += 4) {
        int s0 = g_csr_src[e + 0];
        int s1 = g_csr_src[e + 1];
        int s2 = g_csr_src[e + 2];
        int s3 = g_csr_src[e + 3];
        float2 v0 = __ldg(&x2[s0 * 32 + lane]);
        float2 v1 = __ldg(&x2[s1 * 32 + lane]);
        float2 v2 = __ldg(&x2[s2 * 32 + lane]);
        float2 v3 = __ldg(&x2[s3 * 32 + lane]);
        ax += (v0.x + v1.x) + (v2.x + v3.x);
        ay += (v0.y + v1.y) + (v2.y + v3.y);
    }
    for (; e < end; e++) {
        int s = g_csr_src[e];
        float2 v = __ldg(&x2[s * 32 + lane]);
        ax += v.x; ay += v.y;
    }
    float dinv = (end > start) ? 1.0f / (float)(end - start) : 0.0f;
    reinterpret_cast<float2*>(g_mean)[n * 32 + lane] =
        make_float2(ax * dinv, ay * dinv);
}

// ---------------- K5: fused two-layer GEMM -----------------------------------
// Per block: 128 nodes, 256 threads, 8x4 register tile.
// __launch_bounds__(256, 3): cap regs at 84 -> 3 blocks/SM (was 90 regs / 2 blocks).
__global__ __launch_bounds__(256, 3) void fused_gemm_kernel(
    const float* __restrict__ x,
    const float* __restrict__ W1l, const float* __restrict__ W1r,
    const float* __restrict__ b1,
    const float* __restrict__ W2l, const float* __restrict__ W2r,
    const float* __restrict__ b2,
    float* __restrict__ out)
{
    __shared__ float sA[64][128];   // stage A: operand tile; stage B: h tile
    __shared__ float sB[64][64];    // weight tile (transposed: [k][out])
    __shared__ float sb1[64];
    __shared__ float sb2[32];

    int tid = threadIdx.x;
    int node0 = blockIdx.x * 128;

    if (tid < 64) sb1[tid] = b1[tid];
    if (tid >= 64 && tid < 96) sb2[tid - 64] = b2[tid - 64];
    __syncthreads();

    int tx = tid & 15, ty = tid >> 4;
    float acc[8][4] = {};   // reused for both stages (register diet)

    // ---------------- Stage A: layer-1 GEMM ---------------------------------
    #pragma unroll
    for (int stage = 0; stage < 2; stage++) {
        const float* Asrc = stage ? x : g_mean;
        const float* Bsrc = stage ? W1r : W1l;
        #pragma unroll
        for (int i = 0; i < 8; i++) {
            int idx = tid + i * 256;
            int n = idx >> 4;
            int c = idx & 15;
            int gn = node0 + n;
            float4 v = (gn < N_NODES)
                ? reinterpret_cast<const float4*>(Asrc)[gn * 16 + c]
                : make_float4(0.f, 0.f, 0.f, 0.f);
            sA[c * 4 + 0][n] = v.x; sA[c * 4 + 1][n] = v.y;
            sA[c * 4 + 2][n] = v.z; sA[c * 4 + 3][n] = v.w;
        }
        #pragma unroll
        for (int i = 0; i < 4; i++) {
            int idx = tid + i * 256;
            int j = idx >> 4;
            int c = idx & 15;
            float4 w = reinterpret_cast<const float4*>(Bsrc)[j * 16 + c];
            sB[c * 4 + 0][j] = w.x; sB[c * 4 + 1][j] = w.y;
            sB[c * 4 + 2][j] = w.z; sB[c * 4 + 3][j] = w.w;
        }
        __syncthreads();

        #pragma unroll 8
        for (int k = 0; k < 64; k++) {
            float4 a4a = *reinterpret_cast<const float4*>(&sA[k][ty * 8]);
            float4 a4b = *reinterpret_cast<const float4*>(&sA[k][ty * 8 + 4]);
            float4 b4  = *reinterpret_cast<const float4*>(&sB[k][tx * 4]);
            float a_[8] = {a4a.x, a4a.y, a4a.z, a4a.w, a4b.x, a4b.y, a4b.z, a4b.w};
            float b_[4] = {b4.x, b4.y, b4.z, b4.w};
            #pragma unroll
            for (int i = 0; i < 8; i++)
                #pragma unroll
                for (int j = 0; j < 4; j++)
                    acc[i][j] = fmaf(a_[i], b_[j], acc[i][j]);
        }
        __syncthreads();
    }

    // relu + bias, write h into sA as [out_k][node]; then zero acc for reuse
    #pragma unroll
    for (int i = 0; i < 8; i++) {
        int n = ty * 8 + i;
        #pragma unroll
        for (int j = 0; j < 4; j++) {
            sA[tx * 4 + j][n] = fmaxf(acc[i][j] + sb1[tx * 4 + j], 0.f);
            acc[i][j] = 0.f;
        }
    }

    // load stacked W2 (rows 0..31: W2l, 32..63: W2r)
    #pragma unroll
    for (int i = 0; i < 4; i++) {
        int idx = tid + i * 256;
        int j = idx >> 4;
        int c = idx & 15;
        const float* Bsrc = (j < 32) ? (W2l + j * 64) : (W2r + (j - 32) * 64);
        float4 w = reinterpret_cast<const float4*>(Bsrc)[c];
        sB[c * 4 + 0][j] = w.x; sB[c * 4 + 1][j] = w.y;
        sB[c * 4 + 2][j] = w.z; sB[c * 4 + 3][j] = w.w;
    }
    __syncthreads();

    // ---------------- Stage B: layer-2 GEMM ---------------------------------
    #pragma unroll 8
    for (int k = 0; k < 64; k++) {
        float4 a4a = *reinterpret_cast<const float4*>(&sA[k][ty * 8]);
        float4 a4b = *reinterpret_cast<const float4*>(&sA[k][ty * 8 + 4]);
        float4 b4  = *reinterpret_cast<const float4*>(&sB[k][tx * 4]);
        float a_[8] = {a4a.x, a4a.y, a4a.z, a4a.w, a4b.x, a4b.y, a4b.z, a4b.w};
        float b_[4] = {b4.x, b4.y, b4.z, b4.w};
        #pragma unroll
        for (int i = 0; i < 8; i++)
            #pragma unroll
            for (int j = 0; j < 4; j++)
                acc[i][j] = fmaf(a_[i], b_[j], acc[i][j]);
    }

    #pragma unroll
    for (int i = 0; i < 8; i++) {
        int gn = node0 + ty * 8 + i;
        if (gn < N_NODES) {
            if (tx < 8) {               // p columns -> g_p
                float4 o = make_float4(acc[i][0], acc[i][1], acc[i][2], acc[i][3]);
                reinterpret_cast<float4*>(g_p)[gn * 8 + tx] = o;
            } else {                    // q columns -> out (self term + b2)
                int jc = (tx - 8) * 4;
                float4 o;
                o.x = acc[i][0] + sb2[jc + 0];
                o.y = acc[i][1] + sb2[jc + 1];
                o.z = acc[i][2] + sb2[jc + 2];
                o.w = acc[i][3] + sb2[jc + 3];
                reinterpret_cast<float4*>(out)[gn * 8 + (tx - 8)] = o;
            }
        }
    }
}

// ---------------- K6: gather layer 2 (warp per node) -------------------------
__global__ __launch_bounds__(256) void gather32_kernel(float* __restrict__ out)
{
    int wid = threadIdx.x >> 5, lane = threadIdx.x & 31;
    int n = blockIdx.x * 8 + wid;
    if (n >= N_NODES) return;

    int start = g_rowptr[n], end = g_rowptr[n + 1];

    float a = 0.f;
    int e = start;
    for (; e + 4 <= end; e += 4) {
        int s0 = g_csr_src[e + 0];
        int s1 = g_csr_src[e + 1];
        int s2 = g_csr_src[e + 2];
        int s3 = g_csr_src[e + 3];
        float v0 = __ldg(&g_p[s0 * 32 + lane]);
        float v1 = __ldg(&g_p[s1 * 32 + lane]);
        float v2 = __ldg(&g_p[s2 * 32 + lane]);
        float v3 = __ldg(&g_p[s3 * 32 + lane]);
        a += (v0 + v1) + (v2 + v3);
    }
    for (; e < end; e++) {
        int s = g_csr_src[e];
        a += __ldg(&g_p[s * 32 + lane]);
    }
    float dinv = (end > start) ? 1.0f / (float)(end - start) : 0.0f;
    out[n * 32 + lane] += a * dinv;
}

// ---------------- launch ------------------------------------------------------
extern "C" void kernel_launch(void* const* d_in, const int* in_sizes, int n_in,
                              void* d_out, int out_size)
{
    const float* x    = (const float*)d_in[0];
    const int*   ei1  = (const int*)d_in[1];     // int32 (JAX x64 disabled)
    const int*   ei2  = (const int*)d_in[3];
    const float* W1l  = (const float*)d_in[5];
    const float* b1   = (const float*)d_in[6];
    const float* W1r  = (const float*)d_in[7];
    const float* W2l  = (const float*)d_in[8];
    const float* b2   = (const float*)d_in[9];
    const float* W2r  = (const float*)d_in[10];
    float*       out  = (float*)d_out;

    int E1 = in_sizes[1] / 2;
    int E2 = in_sizes[3] / 2;
    int E  = E1 + E2;

    // CSR build
    zero_deg_kernel<<<(N_NODES + 255) / 256, 256>>>();
    count_deg_kernel<<<(E + 255) / 256, 256>>>(ei1, ei2, E1, E2);
    scan_block_kernel<<<NB_SCAN, 256>>>();
    scan_sums_kernel<<<1, 128>>>();
    scan_add_kernel<<<(N_NODES + 256) / 256, 256>>>(E);
    fill_csr_kernel<<<(E + 255) / 256, 256>>>(ei1, ei2, E1, E2);

    // layer-1 aggregation (gather, no atomics)
    gather64_kernel<<<(N_NODES + 7) / 8, 256>>>(x);

    // fused two-layer GEMM -> g_p, out(self term)
    int nblk = (N_NODES + 127) / 128;
    fused_gemm_kernel<<<nblk, 256>>>(x, W1l, W1r, b1, W2l, W2r, b2, out);

    // layer-2 aggregation (gather, exclusive out += mean)
    gather32_kernel<<<(N_NODES + 7) / 8, 256>>>(out);
}

// round 10
// speedup vs baseline: 5.1161x; 1.0389x over previous
#include <cuda_runtime.h>
#include <cuda_bf16.h>

#define N_NODES 100000
#define MAX_E   1600000
#define NB_SCAN 98            // ceil(100000/1024)

// ---------------- scratch (static device globals; no allocation) ------------
__device__ __align__(16) int   g_degi[N_NODES];        // in-degree (int)
__device__ __align__(16) int   g_rowptr[N_NODES + 1];  // CSR row offsets
__device__ __align__(16) int   g_fill[N_NODES];        // fill cursor
__device__ __align__(16) int   g_blocksum[NB_SCAN + 1];
__device__ __align__(16) int   g_csr_src[MAX_E];       // src per CSR slot
__device__ __align__(16) float g_mean[N_NODES * 64];   // layer-1 neighbor mean
__device__ __align__(16) float g_p[N_NODES * 32];      // h @ W2l^T (l2 messages)

// ---------------- K0: zero degree counters ----------------------------------
__global__ __launch_bounds__(256) void zero_deg_kernel()
{
    int t = blockIdx.x * blockDim.x + threadIdx.x;
    if (t < N_NODES) g_degi[t] = 0;
}

// ---------------- K1: count in-degrees ---------------------------------------
__global__ __launch_bounds__(256) void count_deg_kernel(
    const int* __restrict__ ei1, const int* __restrict__ ei2, int E1, int E2)
{
    int t = blockIdx.x * blockDim.x + threadIdx.x;
    int E = E1 + E2;
    if (t >= E) return;
    int d = (t < E1) ? ei1[t + E1] : ei2[(t - E1) + E2];
    atomicAdd(&g_degi[d], 1);
}

// ---------------- K2a: per-block exclusive scan (1024 items/block) ----------
__global__ __launch_bounds__(256) void scan_block_kernel()
{
    __shared__ int swarp[8];
    int tid = threadIdx.x, lane = tid & 31, wid = tid >> 5;
    int base = blockIdx.x * 1024 + tid * 4;

    int v0 = (base + 0 < N_NODES) ? g_degi[base + 0] : 0;
    int v1 = (base + 1 < N_NODES) ? g_degi[base + 1] : 0;
    int v2 = (base + 2 < N_NODES) ? g_degi[base + 2] : 0;
    int v3 = (base + 3 < N_NODES) ? g_degi[base + 3] : 0;
    int tsum = v0 + v1 + v2 + v3;

    int s = tsum;
    #pragma unroll
    for (int off = 1; off < 32; off <<= 1) {
        int t = __shfl_up_sync(0xffffffffu, s, off);
        if (lane >= off) s += t;
    }
    if (lane == 31) swarp[wid] = s;
    __syncthreads();
    if (tid == 0) {
        int r = 0;
        #pragma unroll
        for (int i = 0; i < 8; i++) { int t = swarp[i]; swarp[i] = r; r += t; }
        g_blocksum[blockIdx.x] = r;                 // block total
    }
    __syncthreads();
    int excl = s - tsum + swarp[wid];               // exclusive within block
    if (base + 0 < N_NODES) g_rowptr[base + 0] = excl;
    if (base + 1 < N_NODES) g_rowptr[base + 1] = excl + v0;
    if (base + 2 < N_NODES) g_rowptr[base + 2] = excl + v0 + v1;
    if (base + 3 < N_NODES) g_rowptr[base + 3] = excl + v0 + v1 + v2;
}

// ---------------- K2b: add block offsets, init fill cursors ------------------
// Each 256-thread block lies entirely inside one 1024-chunk -> uniform offset.
__global__ __launch_bounds__(256) void scan_add_kernel(int E)
{
    __shared__ int soff;
    int t = blockIdx.x * blockDim.x + threadIdx.x;
    int chunk = (blockIdx.x * 256) >> 10;           // uniform per block
    if (threadIdx.x == 0) {
        int r = 0;
        for (int i = 0; i < chunk; i++) r += g_blocksum[i];
        soff = r;
    }
    __syncthreads();
    if (t < N_NODES) {
        int val = g_rowptr[t] + soff;
        g_rowptr[t] = val;
        g_fill[t] = val;
    }
    if (t == N_NODES) g_rowptr[N_NODES] = E;
}

// ---------------- K3: fill CSR slots -----------------------------------------
__global__ __launch_bounds__(256) void fill_csr_kernel(
    const int* __restrict__ ei1, const int* __restrict__ ei2, int E1, int E2)
{
    int t = blockIdx.x * blockDim.x + threadIdx.x;
    int E = E1 + E2;
    if (t >= E) return;
    int s, d;
    if (t < E1) { s = ei1[t];      d = ei1[t + E1]; }
    else        { int u = t - E1;  s = ei2[u];  d = ei2[u + E2]; }
    int pos = atomicAdd(&g_fill[d], 1);
    g_csr_src[pos] = s;
}

// ---------------- K4: gather layer 1 (warp per node) -------------------------
__global__ __launch_bounds__(256) void gather64_kernel(const float* __restrict__ x)
{
    int wid = threadIdx.x >> 5, lane = threadIdx.x & 31;
    int n = blockIdx.x * 8 + wid;
    if (n >= N_NODES) return;

    int start = g_rowptr[n], end = g_rowptr[n + 1];
    const float2* x2 = reinterpret_cast<const float2*>(x);

    float ax = 0.f, ay = 0.f;
    int e = start;
    for (; e + 4 <= end; e += 4) {
        int s0 = g_csr_src[e + 0];
        int s1 = g_csr_src[e + 1];
        int s2 = g_csr_src[e + 2];
        int s3 = g_csr_src[e + 3];
        float2 v0 = __ldg(&x2[s0 * 32 + lane]);
        float2 v1 = __ldg(&x2[s1 * 32 + lane]);
        float2 v2 = __ldg(&x2[s2 * 32 + lane]);
        float2 v3 = __ldg(&x2[s3 * 32 + lane]);
        ax += (v0.x + v1.x) + (v2.x + v3.x);
        ay += (v0.y + v1.y) + (v2.y + v3.y);
    }
    for (; e < end; e++) {
        int s = g_csr_src[e];
        float2 v = __ldg(&x2[s * 32 + lane]);
        ax += v.x; ay += v.y;
    }
    float dinv = (end > start) ? 1.0f / (float)(end - start) : 0.0f;
    reinterpret_cast<float2*>(g_mean)[n * 32 + lane] =
        make_float2(ax * dinv, ay * dinv);
}

// ---------------- K5: fused two-layer GEMM -----------------------------------
// Per block: 128 nodes, 256 threads, 8x4 register tile.
// Stage A operand tile: [k][node] (stride 128).  h tile: [node][k] (stride 72)
// -> float4 h-stores (~4-way) and conflict-free broadcast float4 h-loads.
#define HSTRIDE 72
__global__ __launch_bounds__(256) void fused_gemm_kernel(
    const float* __restrict__ x,
    const float* __restrict__ W1l, const float* __restrict__ W1r,
    const float* __restrict__ b1,
    const float* __restrict__ W2l, const float* __restrict__ W2r,
    const float* __restrict__ b2,
    float* __restrict__ out)
{
    __shared__ float sAbuf[128 * HSTRIDE];   // 9216 floats >= 64*128 (stage A)
    __shared__ float sB[64][64];             // weight tile [k][out]
    __shared__ float sb1[64];
    __shared__ float sb2[32];

    int tid = threadIdx.x;
    int node0 = blockIdx.x * 128;

    if (tid < 64) sb1[tid] = b1[tid];
    if (tid >= 64 && tid < 96) sb2[tid - 64] = b2[tid - 64];
    __syncthreads();

    int tx = tid & 15, ty = tid >> 4;
    float acc[8][4] = {};

    // ---------------- Stage A: layer-1 GEMM ([k][node], stride 128) ---------
    #pragma unroll
    for (int stage = 0; stage < 2; stage++) {
        const float* Asrc = stage ? x : g_mean;
        const float* Bsrc = stage ? W1r : W1l;
        #pragma unroll
        for (int i = 0; i < 8; i++) {
            int idx = tid + i * 256;
            int n = idx >> 4;
            int c = idx & 15;
            int gn = node0 + n;
            float4 v = (gn < N_NODES)
                ? reinterpret_cast<const float4*>(Asrc)[gn * 16 + c]
                : make_float4(0.f, 0.f, 0.f, 0.f);
            sAbuf[(c * 4 + 0) * 128 + n] = v.x;
            sAbuf[(c * 4 + 1) * 128 + n] = v.y;
            sAbuf[(c * 4 + 2) * 128 + n] = v.z;
            sAbuf[(c * 4 + 3) * 128 + n] = v.w;
        }
        #pragma unroll
        for (int i = 0; i < 4; i++) {
            int idx = tid + i * 256;
            int j = idx >> 4;
            int c = idx & 15;
            float4 w = reinterpret_cast<const float4*>(Bsrc)[j * 16 + c];
            sB[c * 4 + 0][j] = w.x; sB[c * 4 + 1][j] = w.y;
            sB[c * 4 + 2][j] = w.z; sB[c * 4 + 3][j] = w.w;
        }
        __syncthreads();

        #pragma unroll 8
        for (int k = 0; k < 64; k++) {
            float4 a4a = *reinterpret_cast<const float4*>(&sAbuf[k * 128 + ty * 8]);
            float4 a4b = *reinterpret_cast<const float4*>(&sAbuf[k * 128 + ty * 8 + 4]);
            float4 b4  = *reinterpret_cast<const float4*>(&sB[k][tx * 4]);
            float a_[8] = {a4a.x, a4a.y, a4a.z, a4a.w, a4b.x, a4b.y, a4b.z, a4b.w};
            float b_[4] = {b4.x, b4.y, b4.z, b4.w};
            #pragma unroll
            for (int i = 0; i < 8; i++)
                #pragma unroll
                for (int j = 0; j < 4; j++)
                    acc[i][j] = fmaf(a_[i], b_[j], acc[i][j]);
        }
        __syncthreads();
    }

    // relu + bias, write h as [node][k] with float4 stores; zero acc for reuse
    #pragma unroll
    for (int i = 0; i < 8; i++) {
        int n = ty * 8 + i;
        float4 hv;
        hv.x = fmaxf(acc[i][0] + sb1[tx * 4 + 0], 0.f);
        hv.y = fmaxf(acc[i][1] + sb1[tx * 4 + 1], 0.f);
        hv.z = fmaxf(acc[i][2] + sb1[tx * 4 + 2], 0.f);
        hv.w = fmaxf(acc[i][3] + sb1[tx * 4 + 3], 0.f);
        *reinterpret_cast<float4*>(&sAbuf[n * HSTRIDE + tx * 4]) = hv;
        acc[i][0] = acc[i][1] = acc[i][2] = acc[i][3] = 0.f;
    }

    // load stacked W2 (rows 0..31: W2l, 32..63: W2r) into sB[k][out]
    #pragma unroll
    for (int i = 0; i < 4; i++) {
        int idx = tid + i * 256;
        int j = idx >> 4;
        int c = idx & 15;
        const float* Bsrc = (j < 32) ? (W2l + j * 64) : (W2r + (j - 32) * 64);
        float4 w = reinterpret_cast<const float4*>(Bsrc)[c];
        sB[c * 4 + 0][j] = w.x; sB[c * 4 + 1][j] = w.y;
        sB[c * 4 + 2][j] = w.z; sB[c * 4 + 3][j] = w.w;
    }
    __syncthreads();

    // ---------------- Stage B: layer-2 GEMM (h[node][k], k-chunked x4) ------
    for (int k0 = 0; k0 < 64; k0 += 4) {
        float4 av[8];
        #pragma unroll
        for (int i = 0; i < 8; i++)
            av[i] = *reinterpret_cast<const float4*>(
                        &sAbuf[(ty * 8 + i) * HSTRIDE + k0]);
        #pragma unroll
        for (int kk = 0; kk < 4; kk++) {
            float4 b4 = *reinterpret_cast<const float4*>(&sB[k0 + kk][tx * 4]);
            float b_[4] = {b4.x, b4.y, b4.z, b4.w};
            #pragma unroll
            for (int i = 0; i < 8; i++) {
                float a = (kk == 0) ? av[i].x : (kk == 1) ? av[i].y
                         : (kk == 2) ? av[i].z : av[i].w;
                #pragma unroll
                for (int j = 0; j < 4; j++)
                    acc[i][j] = fmaf(a, b_[j], acc[i][j]);
            }
        }
    }

    #pragma unroll
    for (int i = 0; i < 8; i++) {
        int gn = node0 + ty * 8 + i;
        if (gn < N_NODES) {
            if (tx < 8) {               // p columns -> g_p
                float4 o = make_float4(acc[i][0], acc[i][1], acc[i][2], acc[i][3]);
                reinterpret_cast<float4*>(g_p)[gn * 8 + tx] = o;
            } else {                    // q columns -> out (self term + b2)
                int jc = (tx - 8) * 4;
                float4 o;
                o.x = acc[i][0] + sb2[jc + 0];
                o.y = acc[i][1] + sb2[jc + 1];
                o.z = acc[i][2] + sb2[jc + 2];
                o.w = acc[i][3] + sb2[jc + 3];
                reinterpret_cast<float4*>(out)[gn * 8 + (tx - 8)] = o;
            }
        }
    }
}

// ---------------- K6: gather layer 2 (warp per node) -------------------------
__global__ __launch_bounds__(256) void gather32_kernel(float* __restrict__ out)
{
    int wid = threadIdx.x >> 5, lane = threadIdx.x & 31;
    int n = blockIdx.x * 8 + wid;
    if (n >= N_NODES) return;

    int start = g_rowptr[n], end = g_rowptr[n + 1];

    float a = 0.f;
    int e = start;
    for (; e + 4 <= end; e += 4) {
        int s0 = g_csr_src[e + 0];
        int s1 = g_csr_src[e + 1];
        int s2 = g_csr_src[e + 2];
        int s3 = g_csr_src[e + 3];
        float v0 = __ldg(&g_p[s0 * 32 + lane]);
        float v1 = __ldg(&g_p[s1 * 32 + lane]);
        float v2 = __ldg(&g_p[s2 * 32 + lane]);
        float v3 = __ldg(&g_p[s3 * 32 + lane]);
        a += (v0 + v1) + (v2 + v3);
    }
    for (; e < end; e++) {
        int s = g_csr_src[e];
        a += __ldg(&g_p[s * 32 + lane]);
    }
    float dinv = (end > start) ? 1.0f / (float)(end - start) : 0.0f;
    out[n * 32 + lane] += a * dinv;
}

// ---------------- launch ------------------------------------------------------
extern "C" void kernel_launch(void* const* d_in, const int* in_sizes, int n_in,
                              void* d_out, int out_size)
{
    const float* x    = (const float*)d_in[0];
    const int*   ei1  = (const int*)d_in[1];     // int32 (JAX x64 disabled)
    const int*   ei2  = (const int*)d_in[3];
    const float* W1l  = (const float*)d_in[5];
    const float* b1   = (const float*)d_in[6];
    const float* W1r  = (const float*)d_in[7];
    const float* W2l  = (const float*)d_in[8];
    const float* b2   = (const float*)d_in[9];
    const float* W2r  = (const float*)d_in[10];
    float*       out  = (float*)d_out;

    int E1 = in_sizes[1] / 2;
    int E2 = in_sizes[3] / 2;
    int E  = E1 + E2;

    // CSR build
    zero_deg_kernel<<<(N_NODES + 255) / 256, 256>>>();
    count_deg_kernel<<<(E + 255) / 256, 256>>>(ei1, ei2, E1, E2);
    scan_block_kernel<<<NB_SCAN, 256>>>();
    scan_add_kernel<<<(N_NODES + 256) / 256, 256>>>(E);
    fill_csr_kernel<<<(E + 255) / 256, 256>>>(ei1, ei2, E1, E2);

    // layer-1 aggregation (gather, no atomics)
    gather64_kernel<<<(N_NODES + 7) / 8, 256>>>(x);

    // fused two-layer GEMM -> g_p, out(self term)
    int nblk = (N_NODES + 127) / 128;
    fused_gemm_kernel<<<nblk, 256>>>(x, W1l, W1r, b1, W2l, W2r, b2, out);

    // layer-2 aggregation (gather, exclusive out += mean)
    gather32_kernel<<<(N_NODES + 7) / 8, 256>>>(out);
}